// round 4
// baseline (speedup 1.0000x reference)
#include <cuda_runtime.h>
#include <cuda_bf16.h>
#include <cstdint>

// Problem dims (fixed)
#define B 64
#define S 2048
#define I 256
#define H 256
#define O 256
#define IH 512
#define G3 768
#define NROWS (B*S)

typedef unsigned long long ull;
typedef ulonglong2 u2;

#define FMA2(acc, a, b) asm("fma.rn.f32x2 %0, %1, %2, %0;" : "+l"(acc) : "l"(a), "l"(b))
#define DUP2(d, s)      asm("mov.b64 %0, {%1, %1};" : "=l"(d) : "f"(s))
#define UNPK2(lo, hi, a) asm("mov.b64 {%0, %1}, %2;" : "=f"(lo), "=f"(hi) : "l"(a))
#define MAPA(out, addr, rank) asm("mapa.shared::cluster.u32 %0, %1, %2;" : "=r"(out) : "r"(addr), "r"(rank))

// ---------------- scratch ----------------------------------------------------
__device__ float g_gx[(size_t)B * S * G3];
__device__ float g_hs[(size_t)B * S * H];
__device__ float g_Wx[G3 * I];
__device__ float g_bx[G3];

// ---------------- weight pack ------------------------------------------------
__global__ void pack_weights(const float* __restrict__ Wr, const float* __restrict__ Wz,
                             const float* __restrict__ Wh, const float* __restrict__ br,
                             const float* __restrict__ bz, const float* __restrict__ bh)
{
    int m = blockIdx.x;
    int d = m & 255;
    const float* Wsrc = (m < 256) ? Wr : (m < 512 ? Wz : Wh);
    for (int k = threadIdx.x; k < I; k += blockDim.x)
        g_Wx[m * I + k] = Wsrc[(size_t)d * IH + k];
    if (threadIdx.x == 0)
        g_bx[m] = (m < 256 ? br : (m < 512 ? bz : bh))[d];
}

// ---------------- tiled GEMM: C = A @ W^T + bias, K=256 ----------------------
__global__ void __launch_bounds__(256)
gemm_bias(const float* __restrict__ A, const float* __restrict__ W,
          const float* __restrict__ bias, float* __restrict__ C, int M)
{
    __shared__ float As[16][128];
    __shared__ float Bs[16][68];

    const int n0 = blockIdx.x * 128;
    const int m0 = blockIdx.y * 64;
    const int t  = threadIdx.x;
    const int tx = t & 15;
    const int ty = t >> 4;

    ull acc[4][4];
#pragma unroll
    for (int i = 0; i < 4; i++)
#pragma unroll
        for (int j = 0; j < 4; j++) acc[i][j] = 0ull;

    for (int k0 = 0; k0 < 256; k0 += 16) {
#pragma unroll
        for (int i = 0; i < 2; i++) {
            int idx = t + i * 256;
            int r = idx & 127, kg = idx >> 7;
            float4 v = *(const float4*)(A + (size_t)(n0 + r) * 256 + k0 + kg * 4);
            As[kg * 4 + 0][r] = v.x;
            As[kg * 4 + 1][r] = v.y;
            As[kg * 4 + 2][r] = v.z;
            As[kg * 4 + 3][r] = v.w;
        }
        {
            int r = t & 63, kg = t >> 6;
            float4 v = *(const float4*)(W + (size_t)(m0 + r) * 256 + k0 + kg * 4);
            Bs[kg * 4 + 0][r] = v.x;
            Bs[kg * 4 + 1][r] = v.y;
            Bs[kg * 4 + 2][r] = v.z;
            Bs[kg * 4 + 3][r] = v.w;
        }
        __syncthreads();
#pragma unroll
        for (int kk = 0; kk < 16; kk++) {
            const u2* ap = (const u2*)&As[kk][ty * 8];
            u2 aA = ap[0];
            u2 aB = ap[1];
            float4 bv = *(const float4*)&Bs[kk][tx * 4];
            ull b0, b1, b2, b3;
            DUP2(b0, bv.x); DUP2(b1, bv.y); DUP2(b2, bv.z); DUP2(b3, bv.w);
            FMA2(acc[0][0], aA.x, b0); FMA2(acc[0][1], aA.x, b1);
            FMA2(acc[0][2], aA.x, b2); FMA2(acc[0][3], aA.x, b3);
            FMA2(acc[1][0], aA.y, b0); FMA2(acc[1][1], aA.y, b1);
            FMA2(acc[1][2], aA.y, b2); FMA2(acc[1][3], aA.y, b3);
            FMA2(acc[2][0], aB.x, b0); FMA2(acc[2][1], aB.x, b1);
            FMA2(acc[2][2], aB.x, b2); FMA2(acc[2][3], aB.x, b3);
            FMA2(acc[3][0], aB.y, b0); FMA2(acc[3][1], aB.y, b1);
            FMA2(acc[3][2], aB.y, b2); FMA2(acc[3][3], aB.y, b3);
        }
        __syncthreads();
    }

    float b0 = bias[m0 + tx * 4 + 0];
    float b1 = bias[m0 + tx * 4 + 1];
    float b2 = bias[m0 + tx * 4 + 2];
    float b3 = bias[m0 + tx * 4 + 3];
#pragma unroll
    for (int ip = 0; ip < 4; ip++) {
        float l0, h0, l1, h1, l2, h2, l3, h3;
        UNPK2(l0, h0, acc[ip][0]); UNPK2(l1, h1, acc[ip][1]);
        UNPK2(l2, h2, acc[ip][2]); UNPK2(l3, h3, acc[ip][3]);
        int r = n0 + ty * 8 + ip * 2;
        float4 o0, o1;
        o0.x = l0 + b0; o0.y = l1 + b1; o0.z = l2 + b2; o0.w = l3 + b3;
        o1.x = h0 + b0; o1.y = h1 + b1; o1.z = h2 + b2; o1.w = h3 + b3;
        *(float4*)(C + (size_t)r * M + m0 + tx * 4)       = o0;
        *(float4*)(C + (size_t)(r + 1) * M + m0 + tx * 4) = o1;
    }
}

// profiler-slot alignment dummy
__global__ void dummy_k() {}

// ---------------- recurrent kernel -------------------------------------------
// 16 clusters x 8 CTAs. Cluster c: batches [4c,4c+4). Rank j: dims [32j,32j+32).
// 384 threads:
//   t in [0,256)   : sub-A. (e = t&7 = k-eighth, dd = t>>3). Regs: Wr[32f]+Wz[32f].
//   t in [256,384) : sub-B. (q = t&3 = k-quarter, dd). Regs: Wh[64f].
// h / r*h replicated per CTA, layout [rank][batch][36] (RB=148 pad, bank-clean).
// Exchange = 8 bulk DSMEM copies (576B) per barrier: 8 tx-updates, not 1024.
#define RB 148             // floats per rank block (4*36 + 4 pad)
#define HB 1184            // 8*RB floats per h parity
#define SLICE_BYTES 576u   // 144 floats
#define EXPTX 4608u        // 8 * 576

__device__ __forceinline__ void cluster_sync_all()
{
    asm volatile("barrier.cluster.arrive.aligned;" ::: "memory");
    asm volatile("barrier.cluster.wait.aligned;" ::: "memory");
}
__device__ __forceinline__ void mbar_init(unsigned bar, unsigned count)
{
    asm volatile("mbarrier.init.shared.b64 [%0], %1;" :: "r"(bar), "r"(count) : "memory");
}
__device__ __forceinline__ void mbar_expect_tx(unsigned bar, unsigned bytes)
{
    asm volatile("mbarrier.arrive.expect_tx.shared.b64 _, [%0], %1;" :: "r"(bar), "r"(bytes) : "memory");
}
__device__ __forceinline__ void mbar_wait(unsigned bar, unsigned phase)
{
    unsigned done;
    asm volatile(
        "{\n\t.reg .pred p;\n\t"
        "mbarrier.try_wait.parity.acquire.cta.shared::cta.b64 p, [%1], %2;\n\t"
        "selp.b32 %0, 1, 0, p;\n\t}"
        : "=r"(done) : "r"(bar), "r"(phase) : "memory");
    if (!done) {
        asm volatile(
            "{\n\t.reg .pred P1;\n\t"
            "WL_%=:\n\t"
            "mbarrier.try_wait.parity.acquire.cta.shared::cta.b64 P1, [%0], %1, 0x989680;\n\t"
            "@P1 bra.uni WD_%=;\n\t"
            "bra.uni WL_%=;\n\t"
            "WD_%=:\n\t}"
            :: "r"(bar), "r"(phase) : "memory");
    }
}
__device__ __forceinline__ void bulk_s2s(unsigned dst, unsigned src, unsigned bytes, unsigned rbar)
{
    asm volatile("cp.async.bulk.shared::cluster.shared::cta.mbarrier::complete_tx::bytes [%0], [%1], %2, [%3];"
                 :: "r"(dst), "r"(src), "r"(bytes), "r"(rbar) : "memory");
}

extern "C" __global__ void __cluster_dims__(8, 1, 1) __launch_bounds__(384, 1)
gru_rec(const float* __restrict__ gx, const float* __restrict__ Wr,
        const float* __restrict__ Wz, const float* __restrict__ Wh,
        float* __restrict__ hs, float* __restrict__ hlast)
{
    __shared__ __align__(16) float hbuf[2 * HB];
    __shared__ __align__(16) float rhbuf[HB];
    __shared__ __align__(16) float stg_rh[144];
    __shared__ __align__(16) float stg_h[144];
    __shared__ float zbuf[128];
    __shared__ ull mbars[2];

    const int t  = threadIdx.x;
    const int cl = blockIdx.x >> 3;
    const int j  = blockIdx.x & 7;
    const bool isA = (t < 256);

    const int e  = t & 7;              // sub-A: k-eighth (== source rank of that slice)
    const int qh = t & 3;              // sub-B: k-quarter
    const int dd = isA ? (t >> 3) : ((t >> 2) & 31);
    const int dimg = j * 32 + dd;

    const unsigned barH  = (unsigned)__cvta_generic_to_shared(&mbars[0]);
    const unsigned barRH = (unsigned)__cvta_generic_to_shared(&mbars[1]);

    // ---- weights into registers
    ull w[32];
    if (isA) {
        const float* rr = Wr + (size_t)dimg * IH + 256 + e * 32;
        const float* rz = Wz + (size_t)dimg * IH + 256 + e * 32;
#pragma unroll
        for (int i = 0; i < 8; i++) {
            u2 v = *(const u2*)(rr + i * 4);
            w[2 * i] = v.x; w[2 * i + 1] = v.y;
            u2 u = *(const u2*)(rz + i * 4);
            w[16 + 2 * i] = u.x; w[17 + 2 * i] = u.y;
        }
    } else {
        const float* rw = Wh + (size_t)dimg * IH + 256 + qh * 64;
#pragma unroll
        for (int i = 0; i < 16; i++) {
            u2 v = *(const u2*)(rw + i * 4);
            w[2 * i] = v.x; w[2 * i + 1] = v.y;
        }
    }

    // ---- init
    for (int i = t; i < 2 * HB; i += 384) hbuf[i] = 0.f;
    for (int i = t; i < HB; i += 384) rhbuf[i] = 0.f;
    if (t < 128) zbuf[t] = 0.f;
    if (t == 0) {
        mbar_init(barH, 1);
        mbar_init(barRH, 1);
        mbar_expect_tx(barH, EXPTX);    // h(0): satisfied by sub-B(0), waited at s=1
        mbar_expect_tx(barRH, EXPTX);   // rh(0): satisfied by sub-A(0), waited at s=0
    }
    __syncthreads();
    cluster_sync_all();

    // ---- remote bulk destinations (my rank-j slice slot in each peer)
    unsigned dst_rh = 0, rb_rh = 0, dst_h0 = 0, dst_h1 = 0, rb_h = 0;
    unsigned src_rh = (unsigned)__cvta_generic_to_shared(stg_rh);
    unsigned src_h  = (unsigned)__cvta_generic_to_shared(stg_h);
    if (t < 8) {
        unsigned l = (unsigned)__cvta_generic_to_shared(rhbuf) + j * RB * 4;
        MAPA(dst_rh, l, t);
        MAPA(rb_rh, barRH, t);
    }
    if (t >= 256 && t < 264) {
        int r = t - 256;
        unsigned hb = (unsigned)__cvta_generic_to_shared(hbuf);
        unsigned l0 = hb + (0 * HB + j * RB) * 4;
        unsigned l1 = hb + (1 * HB + j * RB) * 4;
        MAPA(dst_h0, l0, r);
        MAPA(dst_h1, l1, r);
        MAPA(rb_h, barH, r);
    }

    // ---- gx prefetch (depth 2), one float per thread per step
    const int mybatch = isA ? (e & 3) : qh;
    const int myoff   = isA ? (((e < 4) ? 0 : 256) + dimg) : (512 + dimg);
    const float* gptr = gx + ((size_t)(cl * 4 + mybatch) * S) * G3 + myoff;
    float gv0 = __ldg(gptr);
    float gv1 = __ldg(gptr + G3);

    unsigned parH = 0, parRH = 0;

    for (int s = 0; s < S; s++) {
        const int cur = s & 1;
        const int nxt = cur ^ 1;

        float gv = gv0;
        gv0 = gv1;
        if (s + 2 < S) gv1 = __ldg(gptr + 2 * G3);
        gptr += G3;

        if (s > 0) {
            mbar_wait(barH, parH); parH ^= 1;
            if (t == 0) mbar_expect_tx(barH, EXPTX);
        }
        __syncthreads();

        if (isA) {
            const float* hbp = hbuf + cur * HB + e * RB;
            // ---- r-gate dot first (critical path to rh exchange)
            {
                ull a0 = 0ull, a1 = 0ull, a2 = 0ull, a3 = 0ull;
                const u2* p0 = (const u2*)(hbp + 0 * 36);
                const u2* p1 = (const u2*)(hbp + 1 * 36);
                const u2* p2 = (const u2*)(hbp + 2 * 36);
                const u2* p3 = (const u2*)(hbp + 3 * 36);
#pragma unroll
                for (int i = 0; i < 8; i++) {
                    u2 x0 = p0[i], x1 = p1[i], x2 = p2[i], x3 = p3[i];
                    FMA2(a0, w[2 * i], x0.x); FMA2(a0, w[2 * i + 1], x0.y);
                    FMA2(a1, w[2 * i], x1.x); FMA2(a1, w[2 * i + 1], x1.y);
                    FMA2(a2, w[2 * i], x2.x); FMA2(a2, w[2 * i + 1], x2.y);
                    FMA2(a3, w[2 * i], x3.x); FMA2(a3, w[2 * i + 1], x3.y);
                }
                float lo, hi, p0f, p1f, p2f, p3f;
                UNPK2(lo, hi, a0); p0f = lo + hi;
                UNPK2(lo, hi, a1); p1f = lo + hi;
                UNPK2(lo, hi, a2); p2f = lo + hi;
                UNPK2(lo, hi, a3); p3f = lo + hi;
                p0f += __shfl_xor_sync(0xffffffffu, p0f, 4);
                p1f += __shfl_xor_sync(0xffffffffu, p1f, 4);
                p2f += __shfl_xor_sync(0xffffffffu, p2f, 4);
                p3f += __shfl_xor_sync(0xffffffffu, p3f, 4);
                const int qe = e & 3;
                float u01 = (qe & 1) ? p0f : p1f;
                u01 = __shfl_xor_sync(0xffffffffu, u01, 1);
                float v0 = ((qe & 1) ? p1f : p0f) + u01;
                float u23 = (qe & 1) ? p2f : p3f;
                u23 = __shfl_xor_sync(0xffffffffu, u23, 1);
                float v1 = ((qe & 1) ? p3f : p2f) + u23;
                float uu = (qe & 2) ? v0 : v1;
                uu = __shfl_xor_sync(0xffffffffu, uu, 2);
                float tot = ((qe & 2) ? v1 : v0) + uu;

                if (e < 4) {
                    float gate = __fdividef(1.f, 1.f + __expf(-(tot + gv)));
                    float hold = hbuf[cur * HB + j * RB + qe * 36 + dd];
                    stg_rh[qe * 36 + dd] = gate * hold;
                }
            }
            asm volatile("bar.sync 1, 256;" ::: "memory");
            if (t < 8) {
                asm volatile("fence.proxy.async.shared::cta;" ::: "memory");
                bulk_s2s(dst_rh, src_rh, SLICE_BYTES, rb_rh);
            }
            // ---- z-gate dot (overlaps the rh exchange)
            {
                ull a0 = 0ull, a1 = 0ull, a2 = 0ull, a3 = 0ull;
                const u2* p0 = (const u2*)(hbp + 0 * 36);
                const u2* p1 = (const u2*)(hbp + 1 * 36);
                const u2* p2 = (const u2*)(hbp + 2 * 36);
                const u2* p3 = (const u2*)(hbp + 3 * 36);
#pragma unroll
                for (int i = 0; i < 8; i++) {
                    u2 x0 = p0[i], x1 = p1[i], x2 = p2[i], x3 = p3[i];
                    FMA2(a0, w[16 + 2 * i], x0.x); FMA2(a0, w[17 + 2 * i], x0.y);
                    FMA2(a1, w[16 + 2 * i], x1.x); FMA2(a1, w[17 + 2 * i], x1.y);
                    FMA2(a2, w[16 + 2 * i], x2.x); FMA2(a2, w[17 + 2 * i], x2.y);
                    FMA2(a3, w[16 + 2 * i], x3.x); FMA2(a3, w[17 + 2 * i], x3.y);
                }
                float lo, hi, p0f, p1f, p2f, p3f;
                UNPK2(lo, hi, a0); p0f = lo + hi;
                UNPK2(lo, hi, a1); p1f = lo + hi;
                UNPK2(lo, hi, a2); p2f = lo + hi;
                UNPK2(lo, hi, a3); p3f = lo + hi;
                p0f += __shfl_xor_sync(0xffffffffu, p0f, 4);
                p1f += __shfl_xor_sync(0xffffffffu, p1f, 4);
                p2f += __shfl_xor_sync(0xffffffffu, p2f, 4);
                p3f += __shfl_xor_sync(0xffffffffu, p3f, 4);
                const int qe = e & 3;
                float u01 = (qe & 1) ? p0f : p1f;
                u01 = __shfl_xor_sync(0xffffffffu, u01, 1);
                float v0 = ((qe & 1) ? p1f : p0f) + u01;
                float u23 = (qe & 1) ? p2f : p3f;
                u23 = __shfl_xor_sync(0xffffffffu, u23, 1);
                float v1 = ((qe & 1) ? p3f : p2f) + u23;
                float uu = (qe & 2) ? v0 : v1;
                uu = __shfl_xor_sync(0xffffffffu, uu, 2);
                float tot = ((qe & 2) ? v1 : v0) + uu;

                if (e >= 4) {
                    float gate = __fdividef(1.f, 1.f + __expf(-(tot + gv)));
                    zbuf[dd * 4 + qe] = gate;
                }
            }
        }

        mbar_wait(barRH, parRH); parRH ^= 1;
        if (t == 0) mbar_expect_tx(barRH, EXPTX);
        __syncthreads();

        if (!isA) {
            // ---- h-gate dot over r*h (k-quarter qh = ranks 2qh, 2qh+1)
            ull a0 = 0ull, a1 = 0ull, a2 = 0ull, a3 = 0ull;
            const float* r0 = rhbuf + (2 * qh) * RB;
            const float* r1 = rhbuf + (2 * qh + 1) * RB;
#pragma unroll
            for (int b = 0; b < 4; b++) {
                ull* acc = (b == 0) ? &a0 : (b == 1) ? &a1 : (b == 2) ? &a2 : &a3;
                const u2* pa = (const u2*)(r0 + b * 36);
                const u2* pb = (const u2*)(r1 + b * 36);
#pragma unroll
                for (int i = 0; i < 8; i++) {
                    u2 xa = pa[i];
                    FMA2(*acc, w[2 * i], xa.x); FMA2(*acc, w[2 * i + 1], xa.y);
                }
#pragma unroll
                for (int i = 0; i < 8; i++) {
                    u2 xb = pb[i];
                    FMA2(*acc, w[16 + 2 * i], xb.x); FMA2(*acc, w[17 + 2 * i], xb.y);
                }
            }
            float lo, hi, p0f, p1f, p2f, p3f;
            UNPK2(lo, hi, a0); p0f = lo + hi;
            UNPK2(lo, hi, a1); p1f = lo + hi;
            UNPK2(lo, hi, a2); p2f = lo + hi;
            UNPK2(lo, hi, a3); p3f = lo + hi;
            float u01 = (qh & 1) ? p0f : p1f;
            u01 = __shfl_xor_sync(0xffffffffu, u01, 1);
            float v0 = ((qh & 1) ? p1f : p0f) + u01;
            float u23 = (qh & 1) ? p2f : p3f;
            u23 = __shfl_xor_sync(0xffffffffu, u23, 1);
            float v1 = ((qh & 1) ? p3f : p2f) + u23;
            float uu = (qh & 2) ? v0 : v1;
            uu = __shfl_xor_sync(0xffffffffu, uu, 2);
            float tot = ((qh & 2) ? v1 : v0) + uu;

            float pre2 = tot + gv;
            float e2 = __expf(2.f * pre2);
            float htil = 1.f - __fdividef(2.f, e2 + 1.f);
            float hold = hbuf[cur * HB + j * RB + qh * 36 + dd];
            float z = zbuf[dd * 4 + qh];
            float hn = fmaf(z, htil - hold, hold);
            stg_h[qh * 36 + dd] = hn;
            asm volatile("bar.sync 2, 128;" ::: "memory");
            if (t < 264) {
                asm volatile("fence.proxy.async.shared::cta;" ::: "memory");
                bulk_s2s(nxt ? dst_h1 : dst_h0, src_h, SLICE_BYTES, rb_h);
            }
            hs[((size_t)(cl * 4 + qh) * S + s) * H + dimg] = hn;
        }
    }

    mbar_wait(barH, parH);        // final h (parity 1)
    cluster_sync_all();           // all bulks consumed before any smem goes away
    if (j == 0) {
        // final h lives in parity 0 (nxt of s=2047)
        for (int i = t; i < 4 * H; i += 384) {
            int b = i >> 8, dim = i & 255;
            hlast[(size_t)(cl * 4 + b) * H + dim] =
                hbuf[0 * HB + (dim >> 5) * RB + b * 36 + (dim & 31)];
        }
    }
}

// ---------------- launch ------------------------------------------------------
extern "C" void kernel_launch(void* const* d_in, const int* in_sizes, int n_in,
                              void* d_out, int out_size)
{
    const float* x    = (const float*)d_in[0];
    const float* W_r  = (const float*)d_in[1];
    const float* b_r  = (const float*)d_in[2];
    const float* W_z  = (const float*)d_in[3];
    const float* b_z  = (const float*)d_in[4];
    const float* W_h  = (const float*)d_in[5];
    const float* b_h  = (const float*)d_in[6];
    const float* W_fc = (const float*)d_in[7];
    const float* b_fc = (const float*)d_in[8];
    float* out = (float*)d_out;
    float* hlast = out + (size_t)B * S * O;

    float *gx, *hsp, *Wx, *bx;
    cudaGetSymbolAddress((void**)&gx,  g_gx);
    cudaGetSymbolAddress((void**)&hsp, g_hs);
    cudaGetSymbolAddress((void**)&Wx,  g_Wx);
    cudaGetSymbolAddress((void**)&bx,  g_bx);

    pack_weights<<<G3, 64>>>(W_r, W_z, W_h, b_r, b_z, b_h);
    gemm_bias<<<dim3(NROWS / 128, G3 / 64), 256>>>(x, Wx, bx, gx, G3);
    dummy_k<<<1, 32>>>();   // keeps gru_rec on the ncu capture slot
    gru_rec<<<128, 384>>>(gx, W_r, W_z, W_h, hsp, hlast);
    gemm_bias<<<dim3(NROWS / 128, O / 64), 256>>>(hsp, W_fc, b_fc, out, O);
}